// round 5
// baseline (speedup 1.0000x reference)
#include <cuda_runtime.h>

// ---------------------------------------------------------------------------
// CAM (channel attention module), B=8, C=512, H=W=64, fp32.
//
//   phi   = Wphi   @ x      [b,512,4096]
//   theta = Wtheta @ x
//   g     = Wg     @ x
//   attn  = softmax_d( phi @ theta^T )      [b,512,512]
//   yT    = (attn @ g)^T                    [b,4096,512]  (buffer == permuted view)
//   out   = gamma * (Wmask @ view(yT)) + x  [b,512,4096]
// ---------------------------------------------------------------------------

#define BM 128
#define BN 128
#define BK 16
#define AS_LD (BM + 4)   // padded smem leading dim (keeps float4 alignment)

static const int BATCH = 8;
static const int CH    = 512;
static const int NSP   = 4096;

// scratch (allocation-free rule: __device__ globals)
__device__ float g_phi  [(long)8 * 512 * 4096];
__device__ float g_theta[(long)8 * 512 * 4096];
__device__ float g_gbuf [(long)8 * 512 * 4096];
__device__ float g_attn [(long)8 * 512 * 512];
__device__ float g_yT   [(long)8 * 512 * 4096];

// ---------------------------------------------------------------------------
// Tile loaders.  Layout semantics for a [T_rows=BM/BN] x [BK] tile:
//   LAY==0 : storage [rows][ld], k contiguous  (row-major A, or B^T storage)
//   LAY==1 : storage [K][ld],   rows contiguous (col-major A, or row-major B)
// smem tile is always stored as S[k][row] with leading dim AS_LD.
// ---------------------------------------------------------------------------
template<int LAY>
__device__ __forceinline__ void tile_load(const float* __restrict__ P, int ld,
                                          int r0, int k0, int tid, float4 r[2]) {
#pragma unroll
    for (int i = 0; i < 2; ++i) {
        int f = tid + i * 256;
        if (LAY == 0) {
            int row = f >> 2, kc = (f & 3) << 2;
            r[i] = *(const float4*)(P + (long)(r0 + row) * ld + k0 + kc);
        } else {
            int kr = f >> 5, rc = (f & 31) << 2;
            r[i] = *(const float4*)(P + (long)(k0 + kr) * ld + r0 + rc);
        }
    }
}

template<int LAY>
__device__ __forceinline__ void tile_store(float* __restrict__ S, int tid,
                                           const float4 r[2]) {
#pragma unroll
    for (int i = 0; i < 2; ++i) {
        int f = tid + i * 256;
        if (LAY == 0) {
            int row = f >> 2, kc = (f & 3) << 2;
            S[(kc + 0) * AS_LD + row] = r[i].x;
            S[(kc + 1) * AS_LD + row] = r[i].y;
            S[(kc + 2) * AS_LD + row] = r[i].z;
            S[(kc + 3) * AS_LD + row] = r[i].w;
        } else {
            int kr = f >> 5, rc = (f & 31) << 2;
            *(float4*)(S + kr * AS_LD + rc) = r[i];
        }
    }
}

// ---------------------------------------------------------------------------
// Generic batched SGEMM: C[m][n] = sum_k A[m][k] * B[k][n]
//   LA: 0 -> A storage [M][lda] (k contig); 1 -> [K][lda] (m contig)
//   LB: 0 -> B storage [K][ldb] (n contig); 1 -> [N][ldb] (k contig)
//   EPI: C = scale * acc + add
// All dims assumed divisible by tile sizes (true for this problem).
// ---------------------------------------------------------------------------
template<int LA, int LB, bool EPI>
__global__ __launch_bounds__(256, 2)
void sgemm_kernel(const float* __restrict__ A_, const float* __restrict__ B_,
                  float* __restrict__ C_, int K,
                  int lda, int ldb, int ldc,
                  long sA, long sB, long sC,
                  const float* __restrict__ add_, long sAdd,
                  const float* __restrict__ scale_ptr)
{
    constexpr int LBm = (LB == 0) ? 1 : 0;   // map B layout onto tile loader

    const int bz = blockIdx.z;
    const float* A = A_ + (long)bz * sA;
    const float* B = B_ + (long)bz * sB;
    float*       C = C_ + (long)bz * sC;

    const int m0  = blockIdx.y * BM;
    const int n0  = blockIdx.x * BN;
    const int tid = threadIdx.x;
    const int tx  = tid & 15;
    const int ty  = tid >> 4;

    __shared__ float As[BK * AS_LD];
    __shared__ float Bs[BK * AS_LD];

    float acc[8][8];
#pragma unroll
    for (int i = 0; i < 8; ++i)
#pragma unroll
        for (int j = 0; j < 8; ++j) acc[i][j] = 0.f;

    float4 ra[2], rb[2];

    tile_load<LA >(A, lda, m0, 0, tid, ra);
    tile_load<LBm>(B, ldb, n0, 0, tid, rb);
    tile_store<LA >(As, tid, ra);
    tile_store<LBm>(Bs, tid, rb);
    __syncthreads();

    const int nk = K / BK;
    for (int t = 0; t < nk; ++t) {
        if (t + 1 < nk) {
            int kn = (t + 1) * BK;
            tile_load<LA >(A, lda, m0, kn, tid, ra);
            tile_load<LBm>(B, ldb, n0, kn, tid, rb);
        }
#pragma unroll
        for (int k = 0; k < BK; ++k) {
            const float* arow = &As[k * AS_LD + ty * 8];
            const float* brow = &Bs[k * AS_LD + tx * 8];
            float4 a0 = *(const float4*)(arow);
            float4 a1 = *(const float4*)(arow + 4);
            float4 b0 = *(const float4*)(brow);
            float4 b1 = *(const float4*)(brow + 4);
            float a[8] = {a0.x, a0.y, a0.z, a0.w, a1.x, a1.y, a1.z, a1.w};
            float b[8] = {b0.x, b0.y, b0.z, b0.w, b1.x, b1.y, b1.z, b1.w};
#pragma unroll
            for (int i = 0; i < 8; ++i)
#pragma unroll
                for (int j = 0; j < 8; ++j)
                    acc[i][j] = fmaf(a[i], b[j], acc[i][j]);
        }
        __syncthreads();
        if (t + 1 < nk) {
            tile_store<LA >(As, tid, ra);
            tile_store<LBm>(Bs, tid, rb);
            __syncthreads();
        }
    }

    float scale = 1.f;
    const float* add = nullptr;
    if (EPI) {
        scale = __ldg(scale_ptr);
        add   = add_ + (long)bz * sAdd;
    }

#pragma unroll
    for (int i = 0; i < 8; ++i) {
        int row = m0 + ty * 8 + i;
#pragma unroll
        for (int j = 0; j < 8; j += 4) {
            int col = n0 + tx * 8 + j;
            float4 v = make_float4(acc[i][j], acc[i][j+1], acc[i][j+2], acc[i][j+3]);
            if (EPI) {
                float4 ad = *(const float4*)(add + (long)row * ldc + col);
                v.x = fmaf(v.x, scale, ad.x);
                v.y = fmaf(v.y, scale, ad.y);
                v.z = fmaf(v.z, scale, ad.z);
                v.w = fmaf(v.w, scale, ad.w);
            }
            *(float4*)(C + (long)row * ldc + col) = v;
        }
    }
}

// ---------------------------------------------------------------------------
// Softmax over rows of length 512 (in place). One 256-thread block per row.
// ---------------------------------------------------------------------------
__global__ void softmax512(float* __restrict__ data)
{
    float* row = data + (long)blockIdx.x * 512;
    const int tid = threadIdx.x;
    float v0 = row[tid];
    float v1 = row[tid + 256];

    __shared__ float red[256];
    red[tid] = fmaxf(v0, v1);
    __syncthreads();
#pragma unroll
    for (int s = 128; s > 0; s >>= 1) {
        if (tid < s) red[tid] = fmaxf(red[tid], red[tid + s]);
        __syncthreads();
    }
    float mx = red[0];
    __syncthreads();

    float e0 = expf(v0 - mx);
    float e1 = expf(v1 - mx);
    red[tid] = e0 + e1;
    __syncthreads();
#pragma unroll
    for (int s = 128; s > 0; s >>= 1) {
        if (tid < s) red[tid] += red[tid + s];
        __syncthreads();
    }
    float inv = 1.0f / red[0];
    row[tid]       = e0 * inv;
    row[tid + 256] = e1 * inv;
}

// ---------------------------------------------------------------------------
extern "C" void kernel_launch(void* const* d_in, const int* in_sizes, int n_in,
                              void* d_out, int out_size)
{
    const float* x       = (const float*)d_in[0];
    const float* w_phi   = (const float*)d_in[1];
    const float* w_theta = (const float*)d_in[2];
    const float* w_g     = (const float*)d_in[3];
    const float* w_mask  = (const float*)d_in[4];
    const float* gamma   = (const float*)d_in[5];
    float* out = (float*)d_out;

    float *phi, *theta, *gbuf, *attn, *yT;
    cudaGetSymbolAddress((void**)&phi,   g_phi);
    cudaGetSymbolAddress((void**)&theta, g_theta);
    cudaGetSymbolAddress((void**)&gbuf,  g_gbuf);
    cudaGetSymbolAddress((void**)&attn,  g_attn);
    cudaGetSymbolAddress((void**)&yT,    g_yT);

    const long sBN = (long)CH * NSP;        // per-batch [512 x 4096]
    const long sCC = (long)CH * CH;         // per-batch [512 x 512]
    dim3 tpb(256);

    // 1) phi/theta/g projections: M=512(o), N=4096(n), K=512(c)
    {
        dim3 grd(NSP / BN, CH / BM, BATCH);
        sgemm_kernel<0, 0, false><<<grd, tpb>>>(w_phi,   x, phi,   CH, CH, NSP, NSP,
                                                0, sBN, sBN, nullptr, 0, nullptr);
        sgemm_kernel<0, 0, false><<<grd, tpb>>>(w_theta, x, theta, CH, CH, NSP, NSP,
                                                0, sBN, sBN, nullptr, 0, nullptr);
        sgemm_kernel<0, 0, false><<<grd, tpb>>>(w_g,     x, gbuf,  CH, CH, NSP, NSP,
                                                0, sBN, sBN, nullptr, 0, nullptr);
    }

    // 2) logits: S[c][d] = sum_n phi[c][n] * theta[d][n]
    //    M=512, N=512, K=4096; A row-major, B is [N][K] storage (NT)
    {
        dim3 grd(CH / BN, CH / BM, BATCH);
        sgemm_kernel<0, 1, false><<<grd, tpb>>>(phi, theta, attn, NSP, NSP, NSP, CH,
                                                sBN, sBN, sCC, nullptr, 0, nullptr);
    }

    // 3) softmax over d (row length 512)
    softmax512<<<BATCH * CH, 256>>>(attn);

    // 4) yT[m=n_spatial][j=c] = sum_d g[d][m] * attn[j][d]
    //    M=4096, N=512, K=512; A storage [K][lda] (m contig), B storage [N][K]
    //    yT buffer viewed as [512][4096] row-major == permute+reshape of y.
    {
        dim3 grd(CH / BN, NSP / BM, BATCH);
        sgemm_kernel<1, 1, false><<<grd, tpb>>>(gbuf, attn, yT, CH, NSP, CH, CH,
                                                sBN, sCC, sBN, nullptr, 0, nullptr);
    }

    // 5) out = gamma * (w_mask @ yr) + x ; M=512, N=4096, K=512 (NN + epilogue)
    {
        dim3 grd(NSP / BN, CH / BM, BATCH);
        sgemm_kernel<0, 0, true><<<grd, tpb>>>(w_mask, yT, out, CH, CH, NSP, NSP,
                                               0, sBN, sBN, x, sBN, gamma);
    }
}